// round 1
// baseline (speedup 1.0000x reference)
#include <cuda_runtime.h>
#include <math.h>
#include <stdint.h>

#define FF 128      // frames
#define NP 300      // predictions per frame
#define MT 32       // targets per frame
#define KID 512     // id classes

// ---- static device scratch (no allocations allowed) ----
__device__ float  g_cost[FF * MT * NP];     // [F][M][N] transposed cost, 4.9MB
__device__ int    g_pred_idx[FF * MT];      // matched pred index per target
__device__ double g_part[FF * 3];           // per-frame partial sums: l1, giou, nll

// ============================================================
// Kernel 1: cost matrix. One block per frame, 320 threads.
// cost[m][n] = -2*softmax(pl[n])[lab[m]] + 5*L1(pb[n],tb[m]) - 2*giou(pb[n],tb[m])
// ============================================================
__global__ void cost_kernel(const float* __restrict__ pl,
                            const float* __restrict__ pb,
                            const int*   __restrict__ labels,
                            const float* __restrict__ tbx) {
    int f = blockIdx.x;
    __shared__ float s_tb[MT][4];
    __shared__ int   s_lab[MT];
    int tid = threadIdx.x;
    if (tid < MT) {
        s_lab[tid] = labels[f * MT + tid];
        #pragma unroll
        for (int c = 0; c < 4; ++c) s_tb[tid][c] = tbx[(f * MT + tid) * 4 + c];
    }
    __syncthreads();
    if (tid >= NP) return;
    int n = tid;
    // class probs (C=2 softmax)
    float l0 = pl[(f * NP + n) * 2 + 0];
    float l1 = pl[(f * NP + n) * 2 + 1];
    float mx = fmaxf(l0, l1);
    float e0 = __expf(l0 - mx), e1 = __expf(l1 - mx);
    float inv = 1.0f / (e0 + e1);
    float p0 = e0 * inv, p1 = e1 * inv;
    // pred box
    float cx = pb[(f * NP + n) * 4 + 0];
    float cy = pb[(f * NP + n) * 4 + 1];
    float w  = pb[(f * NP + n) * 4 + 2];
    float h  = pb[(f * NP + n) * 4 + 3];
    float ax0 = cx - 0.5f * w, ay0 = cy - 0.5f * h;
    float ax1 = cx + 0.5f * w, ay1 = cy + 0.5f * h;
    float area1 = (ax1 - ax0) * (ay1 - ay0);

    float* out = g_cost + (size_t)f * (MT * NP);
    #pragma unroll 4
    for (int m = 0; m < MT; ++m) {
        float bcx = s_tb[m][0], bcy = s_tb[m][1], bw = s_tb[m][2], bh = s_tb[m][3];
        float bx0 = bcx - 0.5f * bw, by0 = bcy - 0.5f * bh;
        float bx1 = bcx + 0.5f * bw, by1 = bcy + 0.5f * bh;
        float area2 = (bx1 - bx0) * (by1 - by0);
        float iw = fmaxf(fminf(ax1, bx1) - fmaxf(ax0, bx0), 0.0f);
        float ih = fmaxf(fminf(ay1, by1) - fmaxf(ay0, by0), 0.0f);
        float inter = iw * ih;
        float uni = area1 + area2 - inter;
        float iou = inter / uni;
        float cw = fmaxf(fmaxf(ax1, bx1) - fminf(ax0, bx0), 0.0f);
        float ch = fmaxf(fmaxf(ay1, by1) - fminf(ay0, by0), 0.0f);
        float ac = cw * ch;
        float giou = iou - (ac - uni) / ac;
        float l1c = fabsf(cx - bcx) + fabsf(cy - bcy) + fabsf(w - bw) + fabsf(h - bh);
        float prob = (s_lab[m] == 0) ? p0 : p1;
        out[m * NP + n] = -2.0f * prob + 5.0f * l1c - 2.0f * giou;
    }
}

// ============================================================
// Kernel 2: Jonker-Volgenant per frame. One block per frame, 320 threads.
// Exact mirror of the reference (f64 potentials, strict-< minv update,
// first-index argmin tie-break).
// ============================================================
__global__ void __launch_bounds__(320, 1) hungarian_kernel() {
    const double DINF = 1e300;
    int f = blockIdx.x;
    const float* cost = g_cost + (size_t)f * (MT * NP);
    __shared__ double u[MT + 1];
    __shared__ double v[NP + 1];
    __shared__ double minv[NP + 1];
    __shared__ int    p[NP + 1];
    __shared__ int    way[NP + 1];
    __shared__ unsigned char used[NP + 1];
    __shared__ double wval[10];
    __shared__ int    widx[10];
    __shared__ int    s_j0, s_j1;
    __shared__ double s_delta;

    int tid = threadIdx.x;
    if (tid <= NP) { v[tid] = 0.0; p[tid] = 0; }
    if (tid <= MT) u[tid] = 0.0;
    __syncthreads();

    for (int i = 1; i <= MT; ++i) {
        if (tid == 0) { p[0] = i; s_j0 = 0; }
        if (tid <= NP) { minv[tid] = DINF; used[tid] = 0; }
        __syncthreads();
        while (true) {
            int j0 = s_j0;
            if (tid == 0) used[j0] = 1;
            __syncthreads();
            int i0 = p[j0];
            double ui0 = u[i0];
            double val = DINF;
            int idx = tid;
            if (tid >= 1 && tid <= NP && !used[tid]) {
                double cur = (double)cost[(i0 - 1) * NP + (tid - 1)] - ui0 - v[tid];
                if (cur < minv[tid]) { minv[tid] = cur; way[tid] = j0; }
                val = minv[tid];
            }
            // warp-level argmin (value, then smaller index on ties)
            #pragma unroll
            for (int off = 16; off; off >>= 1) {
                double ov = __shfl_down_sync(0xFFFFFFFFu, val, off);
                int    oi = __shfl_down_sync(0xFFFFFFFFu, idx, off);
                if (ov < val || (ov == val && oi < idx)) { val = ov; idx = oi; }
            }
            int wid = tid >> 5;
            if ((tid & 31) == 0) { wval[wid] = val; widx[wid] = idx; }
            __syncthreads();
            if (tid < 32) {
                val = (tid < 10) ? wval[tid] : DINF;
                idx = (tid < 10) ? widx[tid] : 0;
                #pragma unroll
                for (int off = 8; off; off >>= 1) {
                    double ov = __shfl_down_sync(0xFFFFFFFFu, val, off);
                    int    oi = __shfl_down_sync(0xFFFFFFFFu, idx, off);
                    if (ov < val || (ov == val && oi < idx)) { val = ov; idx = oi; }
                }
                if (tid == 0) { s_j1 = idx; s_delta = val; }
            }
            __syncthreads();
            int j1 = s_j1;
            double delta = s_delta;
            if (tid <= NP) {
                if (used[tid]) { u[p[tid]] += delta; v[tid] -= delta; }
                else if (tid >= 1) minv[tid] -= delta;
            }
            __syncthreads();
            if (tid == 0) s_j0 = j1;
            __syncthreads();
            if (p[j1] == 0) break;
        }
        if (tid == 0) {
            int j0 = s_j0;
            while (j0) { int jn = way[j0]; p[j0] = p[jn]; j0 = jn; }
        }
        __syncthreads();
    }
    if (tid >= 1 && tid <= NP && p[tid] > 0)
        g_pred_idx[f * MT + (p[tid] - 1)] = tid - 1;
}

// ============================================================
// Kernel 3: per-frame loss partials. One block per frame, 1024 threads
// (warp w handles target m=w: warp-reduced logsumexp over 512 id logits,
// lane 0 also computes L1 + pairwise GIoU).
// ============================================================
__global__ void loss_kernel(const float* __restrict__ pb,
                            const float* __restrict__ il,
                            const float* __restrict__ tbx,
                            const int*   __restrict__ tids) {
    int f = blockIdx.x;
    int wid = threadIdx.x >> 5, lane = threadIdx.x & 31;
    __shared__ float s_l1[MT], s_g[MT], s_nll[MT];
    int m = wid;
    int idx = g_pred_idx[f * MT + m];

    const float* row = il + ((size_t)(f * NP + idx)) * KID;
    float x[16];
    float mx = -INFINITY;
    #pragma unroll
    for (int k = 0; k < 16; ++k) { x[k] = row[lane + 32 * k]; mx = fmaxf(mx, x[k]); }
    #pragma unroll
    for (int off = 16; off; off >>= 1) mx = fmaxf(mx, __shfl_xor_sync(0xFFFFFFFFu, mx, off));
    float se = 0.0f;
    #pragma unroll
    for (int k = 0; k < 16; ++k) se += __expf(x[k] - mx);
    #pragma unroll
    for (int off = 16; off; off >>= 1) se += __shfl_xor_sync(0xFFFFFFFFu, se, off);

    if (lane == 0) {
        int t = tids[f * MT + m];
        s_nll[m] = (mx + __logf(se)) - row[t];

        float cx = pb[(f * NP + idx) * 4 + 0];
        float cy = pb[(f * NP + idx) * 4 + 1];
        float w  = pb[(f * NP + idx) * 4 + 2];
        float h  = pb[(f * NP + idx) * 4 + 3];
        float bcx = tbx[(f * MT + m) * 4 + 0];
        float bcy = tbx[(f * MT + m) * 4 + 1];
        float bw  = tbx[(f * MT + m) * 4 + 2];
        float bh  = tbx[(f * MT + m) * 4 + 3];
        s_l1[m] = fabsf(cx - bcx) + fabsf(cy - bcy) + fabsf(w - bw) + fabsf(h - bh);

        float ax0 = cx - 0.5f * w, ay0 = cy - 0.5f * h;
        float ax1 = cx + 0.5f * w, ay1 = cy + 0.5f * h;
        float bx0 = bcx - 0.5f * bw, by0 = bcy - 0.5f * bh;
        float bx1 = bcx + 0.5f * bw, by1 = bcy + 0.5f * bh;
        float area1 = (ax1 - ax0) * (ay1 - ay0);
        float area2 = (bx1 - bx0) * (by1 - by0);
        float iw = fmaxf(fminf(ax1, bx1) - fmaxf(ax0, bx0), 0.0f);
        float ih = fmaxf(fminf(ay1, by1) - fmaxf(ay0, by0), 0.0f);
        float inter = iw * ih;
        float uni = area1 + area2 - inter;
        float iou = inter / uni;
        float cw = fmaxf(fmaxf(ax1, bx1) - fminf(ax0, bx0), 0.0f);
        float ch = fmaxf(fmaxf(ay1, by1) - fminf(ay0, by0), 0.0f);
        float ac = cw * ch;
        s_g[m] = iou - (ac - uni) / ac;
    }
    __syncthreads();
    if (threadIdx.x == 0) {
        double a = 0.0, b = 0.0, c = 0.0;
        for (int k = 0; k < MT; ++k) { a += (double)s_l1[k]; b += (double)s_g[k]; c += (double)s_nll[k]; }
        g_part[f * 3 + 0] = a;
        g_part[f * 3 + 1] = b;
        g_part[f * 3 + 2] = c;
    }
}

// ============================================================
// Kernel 4: deterministic final reduction -> 5 output floats
// ============================================================
__global__ void final_kernel(float* __restrict__ out) {
    if (threadIdx.x == 0 && blockIdx.x == 0) {
        double a = 0.0, b = 0.0, c = 0.0;
        for (int f = 0; f < FF; ++f) {
            a += g_part[f * 3 + 0];
            b += g_part[f * 3 + 1];
            c += g_part[f * 3 + 2];
        }
        double loss_l1   = a / (double)(FF * MT * 4);
        double loss_giou = 1.0 - b / (double)(FF * MT);
        double loss_id   = c / (double)(FF * MT);
        double loss = 5.0 * loss_l1 + 2.0 * loss_giou + 1.0 * loss_id;
        out[0] = (float)loss;
        out[1] = 0.0f;              // focal cls loss is a stub -> 0
        out[2] = (float)loss_l1;
        out[3] = (float)loss_giou;
        out[4] = (float)loss_id;
    }
}

extern "C" void kernel_launch(void* const* d_in, const int* in_sizes, int n_in,
                              void* d_out, int out_size) {
    const float* pred_logits  = (const float*)d_in[0];   // [8,16,300,2]
    const float* pred_boxes   = (const float*)d_in[1];   // [8,16,300,4]
    const float* id_logits    = (const float*)d_in[2];   // [8,16,300,512]
    const int*   target_labels= (const int*)  d_in[3];   // [128,32]
    const float* target_boxes = (const float*)d_in[4];   // [128,32,4]
    const int*   target_ids   = (const int*)  d_in[5];   // [128,32]
    float* out = (float*)d_out;

    cost_kernel<<<FF, 320>>>(pred_logits, pred_boxes, target_labels, target_boxes);
    hungarian_kernel<<<FF, 320>>>();
    loss_kernel<<<FF, 1024>>>(pred_boxes, id_logits, target_boxes, target_ids);
    final_kernel<<<1, 32>>>(out);
}